// round 11
// baseline (speedup 1.0000x reference)
#include <cuda_runtime.h>
#include <cstdint>
#include <math.h>

#define TOKENS 262144      // 4 * 256 * 256
#define CDIM   192
#define QKVN   576
#define NHEADS 6
#define NWINS  4096

__device__ float g_qkv[(size_t)TOKENS * QKVN];
__device__ float g_att[(size_t)TOKENS * CDIM];
__device__ float g_wq[(size_t)QKVN * CDIM];   // tf32-rounded qkv_w
__device__ float g_wp[(size_t)CDIM * CDIM];   // tf32-rounded proj_w

__device__ __forceinline__ uint32_t smem_u32(const void* p) {
    uint32_t a;
    asm("{ .reg .u64 t; cvta.to.shared.u64 t, %1; cvt.u32.u64 %0, t; }" : "=r"(a) : "l"(p));
    return a;
}
__device__ __forceinline__ float to_tf32(float x) {
    asm("cvt.rna.tf32.f32 %0, %1;" : "=f"(x) : "f"(x));
    return x;
}
__device__ __forceinline__ uint32_t frag_r(float x) {   // rna-rounded tf32 bits
    asm("cvt.rna.tf32.f32 %0, %0;" : "+f"(x));
    return __float_as_uint(x);
}
__device__ __forceinline__ void mma_tf32(float* c, const uint32_t* a, const uint32_t* b) {
    asm volatile(
        "mma.sync.aligned.m16n8k8.row.col.f32.tf32.tf32.f32 "
        "{%0,%1,%2,%3}, {%4,%5,%6,%7}, {%8,%9}, {%0,%1,%2,%3};"
        : "+f"(c[0]), "+f"(c[1]), "+f"(c[2]), "+f"(c[3])
        : "r"(a[0]), "r"(a[1]), "r"(a[2]), "r"(a[3]), "r"(b[0]), "r"(b[1]));
}
__device__ __forceinline__ void cpa16(uint32_t dst, const void* src) {
    asm volatile("cp.async.cg.shared.global [%0], [%1], 16;" :: "r"(dst), "l"(src));
}
__device__ __forceinline__ void cpa_commit() {
    asm volatile("cp.async.commit_group;" ::: "memory");
}
template<int N>
__device__ __forceinline__ void cpa_wait() {
    asm volatile("cp.async.wait_group %0;" :: "n"(N) : "memory");
}

// round weights to tf32 once
__global__ void round_weights(const float* __restrict__ qw, const float* __restrict__ pw)
{
    int i = blockIdx.x * 256 + threadIdx.x;
    if (i < QKVN * CDIM) g_wq[i] = to_tf32(qw[i]);
    if (i < CDIM * CDIM) g_wp[i] = to_tf32(pw[i]);
}

// ---------------- warp-mma tf32 GEMM, 2-stage cp.async, wide-N ----------------
// C[m][n] = sum_k A[m][k]*W[n][k] + bias[n]
// Block 128x192, 512 threads / 16 warps (4m x 4n), warp tile 32x48 (same as R8),
// BK=32, K=192 (6 slabs). Halves A re-reads vs BN=96 (3 col-blocks for QKV, 1 for proj).
template<int NOUT, bool ROUND_A>
__global__ __launch_bounds__(512) void gemm_mma(
    const float* __restrict__ A, const float* __restrict__ W,
    const float* __restrict__ bias, float* __restrict__ C)
{
    extern __shared__ __align__(16) float sm[];
    float* Abuf = sm;                       // 2 * 128*36 = 9216
    float* Bbuf = sm + 2 * 4608;            // 2 * 192*36 = 13824
    const uint32_t AbufS = smem_u32(Abuf);
    const uint32_t BbufS = smem_u32(Bbuf);

    const int t    = threadIdx.x;
    const int wid  = t >> 5;
    const int lane = t & 31;
    const int bm   = blockIdx.y * 128;
    const int bn   = blockIdx.x * 192;
    const int m0   = (wid >> 2) * 32;
    const int n0   = (wid & 3) * 48;
    const int gr   = lane >> 2;
    const int gc   = lane & 3;

    float acc[2][6][4];
#pragma unroll
    for (int i = 0; i < 2; ++i)
#pragma unroll
        for (int j = 0; j < 6; ++j)
#pragma unroll
            for (int r = 0; r < 4; ++r) acc[i][j][r] = 0.f;

    auto stage = [&](int slab, int buf) {
        const int k0 = slab * 32;
#pragma unroll
        for (int p = 0; p < 2; ++p) {
            int ci = t + p * 512;
            int r = ci >> 3, c = ci & 7;
            cpa16(AbufS + (uint32_t)(buf * 4608 + r * 36 + c * 4) * 4,
                  A + (size_t)(bm + r) * CDIM + k0 + c * 4);
        }
#pragma unroll
        for (int p = 0; p < 3; ++p) {
            int ci = t + p * 512;
            int r = ci >> 3, c = ci & 7;
            cpa16(BbufS + (uint32_t)(buf * 6912 + r * 36 + c * 4) * 4,
                  W + (size_t)(bn + r) * CDIM + k0 + c * 4);
        }
        cpa_commit();
    };

    stage(0, 0);

#pragma unroll
    for (int s = 0; s < 6; ++s) {
        const int buf = s & 1;
        if (s + 1 < 6) stage(s + 1, buf ^ 1);
        if (s + 1 < 6) cpa_wait<1>(); else cpa_wait<0>();
        __syncthreads();

        const float* As = Abuf + buf * 4608;
        const float* Bs = Bbuf + buf * 6912;
#pragma unroll
        for (int ks4 = 0; ks4 < 4; ++ks4) {
            const int kk = ks4 * 8;
            uint32_t af[2][4], bf[6][2];
#pragma unroll
            for (int mi = 0; mi < 2; ++mi) {
                int rb = m0 + mi * 16 + gr;
                if (ROUND_A) {
                    af[mi][0] = frag_r(As[rb * 36 + kk + gc]);
                    af[mi][1] = frag_r(As[(rb + 8) * 36 + kk + gc]);
                    af[mi][2] = frag_r(As[rb * 36 + kk + gc + 4]);
                    af[mi][3] = frag_r(As[(rb + 8) * 36 + kk + gc + 4]);
                } else {
                    af[mi][0] = __float_as_uint(As[rb * 36 + kk + gc]);
                    af[mi][1] = __float_as_uint(As[(rb + 8) * 36 + kk + gc]);
                    af[mi][2] = __float_as_uint(As[rb * 36 + kk + gc + 4]);
                    af[mi][3] = __float_as_uint(As[(rb + 8) * 36 + kk + gc + 4]);
                }
            }
#pragma unroll
            for (int ni = 0; ni < 6; ++ni) {
                int nb = n0 + ni * 8 + gr;
                bf[ni][0] = __float_as_uint(Bs[nb * 36 + kk + gc]);
                bf[ni][1] = __float_as_uint(Bs[nb * 36 + kk + gc + 4]);
            }
#pragma unroll
            for (int mi = 0; mi < 2; ++mi)
#pragma unroll
                for (int ni = 0; ni < 6; ++ni)
                    mma_tf32(acc[mi][ni], af[mi], bf[ni]);
        }
        __syncthreads();
    }

#pragma unroll
    for (int mi = 0; mi < 2; ++mi) {
        int mr = bm + m0 + mi * 16 + gr;
#pragma unroll
        for (int ni = 0; ni < 6; ++ni) {
            int nc = bn + n0 + ni * 8 + gc * 2;
            float2 bv = __ldg((const float2*)(bias + nc));
            float2 o0 = {acc[mi][ni][0] + bv.x, acc[mi][ni][1] + bv.y};
            float2 o1 = {acc[mi][ni][2] + bv.x, acc[mi][ni][3] + bv.y};
            *(float2*)(C + (size_t)mr * NOUT + nc)       = o0;
            *(float2*)(C + (size_t)(mr + 8) * NOUT + nc) = o1;
        }
    }
}

// ---------------- tensor-core window attention (R8 exact) ----------------
__global__ __launch_bounds__(128) void win_attn(const float* __restrict__ bias)
{
    __shared__ __align__(16) float qs[64][36];   // [tok][d], q*scale (tf32)
    __shared__ __align__(16) float ks_[64][36];  // [tok][d]
    __shared__ __align__(16) float vs[64][40];   // [tok][d], pad 40 -> conflict-free B frags
    __shared__ __align__(16) float ps[64][68];   // softmax probs (64 cols + pad)

    const int pair = blockIdx.x;
    const int head = pair % NHEADS;
    const int win  = pair / NHEADS;
    const int b  = win >> 10;
    const int wy = (win >> 5) & 31;
    const int wx = win & 31;

    const int t    = threadIdx.x;
    const int wid  = t >> 5;
    const int lane = t & 31;
    const int gr   = lane >> 2;
    const int gc   = lane & 3;
    const float scale = 0.17677669529663687f;

#pragma unroll
    for (int i = 0; i < 4; ++i) {
        int idx = t + i * 128;
        int p = idx >> 3;
        int c = idx & 7;
        int h = wy * 8 + (p >> 3);
        int w = wx * 8 + (p & 7);
        const float* base = g_qkv + (size_t)(b * 65536 + h * 256 + w) * QKVN + head * 32 + c * 4;
        float4 qv = *(const float4*)(base);
        float4 kv = *(const float4*)(base + CDIM);
        float4 vv = *(const float4*)(base + 2 * CDIM);
        qs[p][c*4+0] = to_tf32(qv.x * scale); qs[p][c*4+1] = to_tf32(qv.y * scale);
        qs[p][c*4+2] = to_tf32(qv.z * scale); qs[p][c*4+3] = to_tf32(qv.w * scale);
        ks_[p][c*4+0] = to_tf32(kv.x); ks_[p][c*4+1] = to_tf32(kv.y);
        ks_[p][c*4+2] = to_tf32(kv.z); ks_[p][c*4+3] = to_tf32(kv.w);
        vs[p][c*4+0] = to_tf32(vv.x); vs[p][c*4+1] = to_tf32(vv.y);
        vs[p][c*4+2] = to_tf32(vv.z); vs[p][c*4+3] = to_tf32(vv.w);
    }
    __syncthreads();

    const int m0 = wid * 16;
    float s[8][4];
#pragma unroll
    for (int ni = 0; ni < 8; ++ni)
#pragma unroll
        for (int r = 0; r < 4; ++r) s[ni][r] = 0.f;

#pragma unroll
    for (int ks4 = 0; ks4 < 4; ++ks4) {
        const int kc = ks4 * 8;
        uint32_t a[4];
        a[0] = __float_as_uint(qs[m0 + gr][kc + gc]);
        a[1] = __float_as_uint(qs[m0 + gr + 8][kc + gc]);
        a[2] = __float_as_uint(qs[m0 + gr][kc + gc + 4]);
        a[3] = __float_as_uint(qs[m0 + gr + 8][kc + gc + 4]);
#pragma unroll
        for (int ni = 0; ni < 8; ++ni) {
            uint32_t bfr[2];
            bfr[0] = __float_as_uint(ks_[ni * 8 + gr][kc + gc]);
            bfr[1] = __float_as_uint(ks_[ni * 8 + gr][kc + gc + 4]);
            mma_tf32(s[ni], a, bfr);
        }
    }

    const int r0 = m0 + gr;
    const int r1 = r0 + 8;
    const float* bp = bias + head * 4096;
    float mx0 = -1e30f, mx1 = -1e30f;
#pragma unroll
    for (int ni = 0; ni < 8; ++ni) {
        float2 b0 = __ldg((const float2*)(bp + r0 * 64 + ni * 8 + gc * 2));
        float2 b1 = __ldg((const float2*)(bp + r1 * 64 + ni * 8 + gc * 2));
        s[ni][0] += b0.x; s[ni][1] += b0.y;
        s[ni][2] += b1.x; s[ni][3] += b1.y;
        mx0 = fmaxf(mx0, fmaxf(s[ni][0], s[ni][1]));
        mx1 = fmaxf(mx1, fmaxf(s[ni][2], s[ni][3]));
    }
    mx0 = fmaxf(mx0, __shfl_xor_sync(0xffffffffu, mx0, 1));
    mx0 = fmaxf(mx0, __shfl_xor_sync(0xffffffffu, mx0, 2));
    mx1 = fmaxf(mx1, __shfl_xor_sync(0xffffffffu, mx1, 1));
    mx1 = fmaxf(mx1, __shfl_xor_sync(0xffffffffu, mx1, 2));

    float sum0 = 0.f, sum1 = 0.f;
#pragma unroll
    for (int ni = 0; ni < 8; ++ni) {
        s[ni][0] = __expf(s[ni][0] - mx0);
        s[ni][1] = __expf(s[ni][1] - mx0);
        s[ni][2] = __expf(s[ni][2] - mx1);
        s[ni][3] = __expf(s[ni][3] - mx1);
        sum0 += s[ni][0] + s[ni][1];
        sum1 += s[ni][2] + s[ni][3];
    }
    sum0 += __shfl_xor_sync(0xffffffffu, sum0, 1);
    sum0 += __shfl_xor_sync(0xffffffffu, sum0, 2);
    sum1 += __shfl_xor_sync(0xffffffffu, sum1, 1);
    sum1 += __shfl_xor_sync(0xffffffffu, sum1, 2);
    const float inv0 = 1.f / sum0;
    const float inv1 = 1.f / sum1;

#pragma unroll
    for (int ni = 0; ni < 8; ++ni) {
        ps[r0][ni * 8 + gc * 2]     = to_tf32(s[ni][0] * inv0);
        ps[r0][ni * 8 + gc * 2 + 1] = to_tf32(s[ni][1] * inv0);
        ps[r1][ni * 8 + gc * 2]     = to_tf32(s[ni][2] * inv1);
        ps[r1][ni * 8 + gc * 2 + 1] = to_tf32(s[ni][3] * inv1);
    }
    __syncwarp();

    float o[4][4];
#pragma unroll
    for (int ni = 0; ni < 4; ++ni)
#pragma unroll
        for (int r = 0; r < 4; ++r) o[ni][r] = 0.f;

#pragma unroll
    for (int ks8 = 0; ks8 < 8; ++ks8) {
        const int kc = ks8 * 8;
        uint32_t a[4];
        a[0] = __float_as_uint(ps[m0 + gr][kc + gc]);
        a[1] = __float_as_uint(ps[m0 + gr + 8][kc + gc]);
        a[2] = __float_as_uint(ps[m0 + gr][kc + gc + 4]);
        a[3] = __float_as_uint(ps[m0 + gr + 8][kc + gc + 4]);
#pragma unroll
        for (int ni = 0; ni < 4; ++ni) {
            uint32_t bfr[2];
            bfr[0] = __float_as_uint(vs[kc + gc][ni * 8 + gr]);
            bfr[1] = __float_as_uint(vs[kc + gc + 4][ni * 8 + gr]);
            mma_tf32(o[ni], a, bfr);
        }
    }

    {
        int h0 = wy * 8 + (r0 >> 3), w0 = wx * 8 + (r0 & 7);
        int h1 = wy * 8 + (r1 >> 3), w1 = wx * 8 + (r1 & 7);
        size_t tok0 = (size_t)(b * 65536 + h0 * 256 + w0) * CDIM + head * 32;
        size_t tok1 = (size_t)(b * 65536 + h1 * 256 + w1) * CDIM + head * 32;
#pragma unroll
        for (int ni = 0; ni < 4; ++ni) {
            int d = ni * 8 + gc * 2;
            *(float2*)(g_att + tok0 + d) = make_float2(to_tf32(o[ni][0]), to_tf32(o[ni][1]));
            *(float2*)(g_att + tok1 + d) = make_float2(to_tf32(o[ni][2]), to_tf32(o[ni][3]));
        }
    }
}

extern "C" void kernel_launch(void* const* d_in, const int* in_sizes, int n_in,
                              void* d_out, int out_size)
{
    const float* x      = (const float*)d_in[0];
    const float* qkv_w  = (const float*)d_in[1];
    const float* qkv_b  = (const float*)d_in[2];
    const float* proj_w = (const float*)d_in[3];
    const float* proj_b = (const float*)d_in[4];
    const float* bias   = (const float*)d_in[5];
    float* out = (float*)d_out;

    float *qkv_p = nullptr, *att_p = nullptr, *wq_p = nullptr, *wp_p = nullptr;
    cudaGetSymbolAddress((void**)&qkv_p, g_qkv);
    cudaGetSymbolAddress((void**)&att_p, g_att);
    cudaGetSymbolAddress((void**)&wq_p, g_wq);
    cudaGetSymbolAddress((void**)&wp_p, g_wp);

    const int smem_bytes = (2 * 4608 + 2 * 6912) * 4;   // 92160
    cudaFuncSetAttribute(gemm_mma<QKVN, true>,  cudaFuncAttributeMaxDynamicSharedMemorySize, smem_bytes);
    cudaFuncSetAttribute(gemm_mma<CDIM, false>, cudaFuncAttributeMaxDynamicSharedMemorySize, smem_bytes);

    // 0) round weights to tf32 (tiny)
    round_weights<<<(QKVN * CDIM + 255) / 256, 256>>>(qkv_w, proj_w);

    // 1) QKV GEMM: [262144,192] x [576,192]^T + b   (A rounded per-fragment)
    dim3 g1(QKVN / 192, TOKENS / 128);
    gemm_mma<QKVN, true><<<g1, 512, smem_bytes>>>(x, wq_p, qkv_b, qkv_p);

    // 2) Windowed attention (writes tf32-rounded g_att)
    win_attn<<<NWINS * NHEADS, 128>>>(bias);

    // 3) Proj GEMM: [262144,192] x [192,192]^T + b  (both operands pre-rounded)
    dim3 g3(CDIM / 192, TOKENS / 128);
    gemm_mma<CDIM, false><<<g3, 512, smem_bytes>>>(att_p, wp_p, proj_b, out);
}

// round 13
// speedup vs baseline: 1.1020x; 1.1020x over previous
#include <cuda_runtime.h>
#include <cstdint>
#include <math.h>

#define TOKENS 262144      // 4 * 256 * 256
#define CDIM   192
#define QKVN   576
#define NHEADS 6
#define NWINS  4096

__device__ float g_qkv[(size_t)TOKENS * QKVN];
__device__ float g_att[(size_t)TOKENS * CDIM];
__device__ float g_wq[(size_t)QKVN * CDIM];   // tf32-rounded qkv_w
__device__ float g_wp[(size_t)CDIM * CDIM];   // tf32-rounded proj_w

__device__ __forceinline__ uint32_t smem_u32(const void* p) {
    uint32_t a;
    asm("{ .reg .u64 t; cvta.to.shared.u64 t, %1; cvt.u32.u64 %0, t; }" : "=r"(a) : "l"(p));
    return a;
}
__device__ __forceinline__ float to_tf32(float x) {
    asm("cvt.rna.tf32.f32 %0, %1;" : "=f"(x) : "f"(x));
    return x;
}
__device__ __forceinline__ uint32_t frag_r(float x) {   // rna-rounded tf32 bits
    asm("cvt.rna.tf32.f32 %0, %0;" : "+f"(x));
    return __float_as_uint(x);
}
__device__ __forceinline__ void mma_tf32(float* c, const uint32_t* a, const uint32_t* b) {
    asm volatile(
        "mma.sync.aligned.m16n8k8.row.col.f32.tf32.tf32.f32 "
        "{%0,%1,%2,%3}, {%4,%5,%6,%7}, {%8,%9}, {%0,%1,%2,%3};"
        : "+f"(c[0]), "+f"(c[1]), "+f"(c[2]), "+f"(c[3])
        : "r"(a[0]), "r"(a[1]), "r"(a[2]), "r"(a[3]), "r"(b[0]), "r"(b[1]));
}
__device__ __forceinline__ void cpa16(uint32_t dst, const void* src) {
    asm volatile("cp.async.cg.shared.global [%0], [%1], 16;" :: "r"(dst), "l"(src));
}
__device__ __forceinline__ void cpa_commit() {
    asm volatile("cp.async.commit_group;" ::: "memory");
}
template<int N>
__device__ __forceinline__ void cpa_wait() {
    asm volatile("cp.async.wait_group %0;" :: "n"(N) : "memory");
}

// round weights to tf32 once
__global__ void round_weights(const float* __restrict__ qw, const float* __restrict__ pw)
{
    int i = blockIdx.x * 256 + threadIdx.x;
    if (i < QKVN * CDIM) g_wq[i] = to_tf32(qw[i]);
    if (i < CDIM * CDIM) g_wp[i] = to_tf32(pw[i]);
}

// ---------------- warp-mma tf32 GEMM (R8 shapes + fragment double-buffering) ----------------
// C[m][n] = sum_k A[m][k]*W[n][k] + bias[n]
// Block 128x96, 8 warps (4m x 2n), warp tile 32x48, BK=32, K=192 (6 slabs).
// Inner loop: register-double-buffered fragments (load ks4+1 while MMA-ing ks4)
// to overlap LDS latency with tensor-pipe work.
template<int NOUT, bool ROUND_A>
__global__ __launch_bounds__(256, 2) void gemm_mma(
    const float* __restrict__ A, const float* __restrict__ W,
    const float* __restrict__ bias, float* __restrict__ C)
{
    extern __shared__ __align__(16) float sm[];
    float* Abuf = sm;                       // 2 * 128*36
    float* Bbuf = sm + 2 * 4608;            // 2 *  96*36
    const uint32_t AbufS = smem_u32(Abuf);
    const uint32_t BbufS = smem_u32(Bbuf);

    const int t    = threadIdx.x;
    const int wid  = t >> 5;
    const int lane = t & 31;
    const int bm   = blockIdx.y * 128;
    const int bn   = blockIdx.x * 96;
    const int m0   = (wid >> 1) * 32;
    const int n0   = (wid & 1) * 48;
    const int gr   = lane >> 2;
    const int gc   = lane & 3;

    float acc[2][6][4];
#pragma unroll
    for (int i = 0; i < 2; ++i)
#pragma unroll
        for (int j = 0; j < 6; ++j)
#pragma unroll
            for (int r = 0; r < 4; ++r) acc[i][j][r] = 0.f;

    auto stage = [&](int slab, int buf) {
        const int k0 = slab * 32;
#pragma unroll
        for (int p = 0; p < 4; ++p) {
            int ci = t + p * 256;
            int r = ci >> 3, c = ci & 7;
            cpa16(AbufS + (uint32_t)(buf * 4608 + r * 36 + c * 4) * 4,
                  A + (size_t)(bm + r) * CDIM + k0 + c * 4);
        }
#pragma unroll
        for (int p = 0; p < 3; ++p) {
            int ci = t + p * 256;
            int r = ci >> 3, c = ci & 7;
            cpa16(BbufS + (uint32_t)(buf * 3456 + r * 36 + c * 4) * 4,
                  W + (size_t)(bn + r) * CDIM + k0 + c * 4);
        }
        cpa_commit();
    };

    stage(0, 0);

#pragma unroll
    for (int s = 0; s < 6; ++s) {
        const int buf = s & 1;
        if (s + 1 < 6) stage(s + 1, buf ^ 1);
        if (s + 1 < 6) cpa_wait<1>(); else cpa_wait<0>();
        __syncthreads();

        const float* As = Abuf + buf * 4608;
        const float* Bs = Bbuf + buf * 3456;

        uint32_t af[2][2][4], bf[2][6][2];   // double-buffered fragments

        auto load_frags = [&](int ks4, uint32_t (*afd)[4], uint32_t (*bfd)[2]) {
            const int kk = ks4 * 8;
#pragma unroll
            for (int mi = 0; mi < 2; ++mi) {
                int rb = m0 + mi * 16 + gr;
                if (ROUND_A) {
                    afd[mi][0] = frag_r(As[rb * 36 + kk + gc]);
                    afd[mi][1] = frag_r(As[(rb + 8) * 36 + kk + gc]);
                    afd[mi][2] = frag_r(As[rb * 36 + kk + gc + 4]);
                    afd[mi][3] = frag_r(As[(rb + 8) * 36 + kk + gc + 4]);
                } else {
                    afd[mi][0] = __float_as_uint(As[rb * 36 + kk + gc]);
                    afd[mi][1] = __float_as_uint(As[(rb + 8) * 36 + kk + gc]);
                    afd[mi][2] = __float_as_uint(As[rb * 36 + kk + gc + 4]);
                    afd[mi][3] = __float_as_uint(As[(rb + 8) * 36 + kk + gc + 4]);
                }
            }
#pragma unroll
            for (int ni = 0; ni < 6; ++ni) {
                int nb = n0 + ni * 8 + gr;
                bfd[ni][0] = __float_as_uint(Bs[nb * 36 + kk + gc]);
                bfd[ni][1] = __float_as_uint(Bs[nb * 36 + kk + gc + 4]);
            }
        };

        load_frags(0, af[0], bf[0]);
#pragma unroll
        for (int ks4 = 0; ks4 < 4; ++ks4) {
            const int cur = ks4 & 1;
            if (ks4 < 3) load_frags(ks4 + 1, af[cur ^ 1], bf[cur ^ 1]);
#pragma unroll
            for (int mi = 0; mi < 2; ++mi)
#pragma unroll
                for (int ni = 0; ni < 6; ++ni)
                    mma_tf32(acc[mi][ni], af[cur][mi], bf[cur][ni]);
        }
        __syncthreads();
    }

#pragma unroll
    for (int mi = 0; mi < 2; ++mi) {
        int mr = bm + m0 + mi * 16 + gr;
#pragma unroll
        for (int ni = 0; ni < 6; ++ni) {
            int nc = bn + n0 + ni * 8 + gc * 2;
            float2 bv = __ldg((const float2*)(bias + nc));
            float2 o0 = {acc[mi][ni][0] + bv.x, acc[mi][ni][1] + bv.y};
            float2 o1 = {acc[mi][ni][2] + bv.x, acc[mi][ni][3] + bv.y};
            *(float2*)(C + (size_t)mr * NOUT + nc)       = o0;
            *(float2*)(C + (size_t)(mr + 8) * NOUT + nc) = o1;
        }
    }
}

// ---------------- tensor-core window attention (R8 exact) ----------------
__global__ __launch_bounds__(128) void win_attn(const float* __restrict__ bias)
{
    __shared__ __align__(16) float qs[64][36];   // [tok][d], q*scale (tf32)
    __shared__ __align__(16) float ks_[64][36];  // [tok][d]
    __shared__ __align__(16) float vs[64][40];   // [tok][d], pad 40 -> conflict-free B frags
    __shared__ __align__(16) float ps[64][68];   // softmax probs (64 cols + pad)

    const int pair = blockIdx.x;
    const int head = pair % NHEADS;
    const int win  = pair / NHEADS;
    const int b  = win >> 10;
    const int wy = (win >> 5) & 31;
    const int wx = win & 31;

    const int t    = threadIdx.x;
    const int wid  = t >> 5;
    const int lane = t & 31;
    const int gr   = lane >> 2;
    const int gc   = lane & 3;
    const float scale = 0.17677669529663687f;

#pragma unroll
    for (int i = 0; i < 4; ++i) {
        int idx = t + i * 128;
        int p = idx >> 3;
        int c = idx & 7;
        int h = wy * 8 + (p >> 3);
        int w = wx * 8 + (p & 7);
        const float* base = g_qkv + (size_t)(b * 65536 + h * 256 + w) * QKVN + head * 32 + c * 4;
        float4 qv = *(const float4*)(base);
        float4 kv = *(const float4*)(base + CDIM);
        float4 vv = *(const float4*)(base + 2 * CDIM);
        qs[p][c*4+0] = to_tf32(qv.x * scale); qs[p][c*4+1] = to_tf32(qv.y * scale);
        qs[p][c*4+2] = to_tf32(qv.z * scale); qs[p][c*4+3] = to_tf32(qv.w * scale);
        ks_[p][c*4+0] = to_tf32(kv.x); ks_[p][c*4+1] = to_tf32(kv.y);
        ks_[p][c*4+2] = to_tf32(kv.z); ks_[p][c*4+3] = to_tf32(kv.w);
        vs[p][c*4+0] = to_tf32(vv.x); vs[p][c*4+1] = to_tf32(vv.y);
        vs[p][c*4+2] = to_tf32(vv.z); vs[p][c*4+3] = to_tf32(vv.w);
    }
    __syncthreads();

    const int m0 = wid * 16;
    float s[8][4];
#pragma unroll
    for (int ni = 0; ni < 8; ++ni)
#pragma unroll
        for (int r = 0; r < 4; ++r) s[ni][r] = 0.f;

#pragma unroll
    for (int ks4 = 0; ks4 < 4; ++ks4) {
        const int kc = ks4 * 8;
        uint32_t a[4];
        a[0] = __float_as_uint(qs[m0 + gr][kc + gc]);
        a[1] = __float_as_uint(qs[m0 + gr + 8][kc + gc]);
        a[2] = __float_as_uint(qs[m0 + gr][kc + gc + 4]);
        a[3] = __float_as_uint(qs[m0 + gr + 8][kc + gc + 4]);
#pragma unroll
        for (int ni = 0; ni < 8; ++ni) {
            uint32_t bfr[2];
            bfr[0] = __float_as_uint(ks_[ni * 8 + gr][kc + gc]);
            bfr[1] = __float_as_uint(ks_[ni * 8 + gr][kc + gc + 4]);
            mma_tf32(s[ni], a, bfr);
        }
    }

    const int r0 = m0 + gr;
    const int r1 = r0 + 8;
    const float* bp = bias + head * 4096;
    float mx0 = -1e30f, mx1 = -1e30f;
#pragma unroll
    for (int ni = 0; ni < 8; ++ni) {
        float2 b0 = __ldg((const float2*)(bp + r0 * 64 + ni * 8 + gc * 2));
        float2 b1 = __ldg((const float2*)(bp + r1 * 64 + ni * 8 + gc * 2));
        s[ni][0] += b0.x; s[ni][1] += b0.y;
        s[ni][2] += b1.x; s[ni][3] += b1.y;
        mx0 = fmaxf(mx0, fmaxf(s[ni][0], s[ni][1]));
        mx1 = fmaxf(mx1, fmaxf(s[ni][2], s[ni][3]));
    }
    mx0 = fmaxf(mx0, __shfl_xor_sync(0xffffffffu, mx0, 1));
    mx0 = fmaxf(mx0, __shfl_xor_sync(0xffffffffu, mx0, 2));
    mx1 = fmaxf(mx1, __shfl_xor_sync(0xffffffffu, mx1, 1));
    mx1 = fmaxf(mx1, __shfl_xor_sync(0xffffffffu, mx1, 2));

    float sum0 = 0.f, sum1 = 0.f;
#pragma unroll
    for (int ni = 0; ni < 8; ++ni) {
        s[ni][0] = __expf(s[ni][0] - mx0);
        s[ni][1] = __expf(s[ni][1] - mx0);
        s[ni][2] = __expf(s[ni][2] - mx1);
        s[ni][3] = __expf(s[ni][3] - mx1);
        sum0 += s[ni][0] + s[ni][1];
        sum1 += s[ni][2] + s[ni][3];
    }
    sum0 += __shfl_xor_sync(0xffffffffu, sum0, 1);
    sum0 += __shfl_xor_sync(0xffffffffu, sum0, 2);
    sum1 += __shfl_xor_sync(0xffffffffu, sum1, 1);
    sum1 += __shfl_xor_sync(0xffffffffu, sum1, 2);
    const float inv0 = 1.f / sum0;
    const float inv1 = 1.f / sum1;

#pragma unroll
    for (int ni = 0; ni < 8; ++ni) {
        ps[r0][ni * 8 + gc * 2]     = to_tf32(s[ni][0] * inv0);
        ps[r0][ni * 8 + gc * 2 + 1] = to_tf32(s[ni][1] * inv0);
        ps[r1][ni * 8 + gc * 2]     = to_tf32(s[ni][2] * inv1);
        ps[r1][ni * 8 + gc * 2 + 1] = to_tf32(s[ni][3] * inv1);
    }
    __syncwarp();

    float o[4][4];
#pragma unroll
    for (int ni = 0; ni < 4; ++ni)
#pragma unroll
        for (int r = 0; r < 4; ++r) o[ni][r] = 0.f;

#pragma unroll
    for (int ks8 = 0; ks8 < 8; ++ks8) {
        const int kc = ks8 * 8;
        uint32_t a[4];
        a[0] = __float_as_uint(ps[m0 + gr][kc + gc]);
        a[1] = __float_as_uint(ps[m0 + gr + 8][kc + gc]);
        a[2] = __float_as_uint(ps[m0 + gr][kc + gc + 4]);
        a[3] = __float_as_uint(ps[m0 + gr + 8][kc + gc + 4]);
#pragma unroll
        for (int ni = 0; ni < 4; ++ni) {
            uint32_t bfr[2];
            bfr[0] = __float_as_uint(vs[kc + gc][ni * 8 + gr]);
            bfr[1] = __float_as_uint(vs[kc + gc + 4][ni * 8 + gr]);
            mma_tf32(o[ni], a, bfr);
        }
    }

    {
        int h0 = wy * 8 + (r0 >> 3), w0 = wx * 8 + (r0 & 7);
        int h1 = wy * 8 + (r1 >> 3), w1 = wx * 8 + (r1 & 7);
        size_t tok0 = (size_t)(b * 65536 + h0 * 256 + w0) * CDIM + head * 32;
        size_t tok1 = (size_t)(b * 65536 + h1 * 256 + w1) * CDIM + head * 32;
#pragma unroll
        for (int ni = 0; ni < 4; ++ni) {
            int d = ni * 8 + gc * 2;
            *(float2*)(g_att + tok0 + d) = make_float2(to_tf32(o[ni][0]), to_tf32(o[ni][1]));
            *(float2*)(g_att + tok1 + d) = make_float2(to_tf32(o[ni][2]), to_tf32(o[ni][3]));
        }
    }
}

extern "C" void kernel_launch(void* const* d_in, const int* in_sizes, int n_in,
                              void* d_out, int out_size)
{
    const float* x      = (const float*)d_in[0];
    const float* qkv_w  = (const float*)d_in[1];
    const float* qkv_b  = (const float*)d_in[2];
    const float* proj_w = (const float*)d_in[3];
    const float* proj_b = (const float*)d_in[4];
    const float* bias   = (const float*)d_in[5];
    float* out = (float*)d_out;

    float *qkv_p = nullptr, *att_p = nullptr, *wq_p = nullptr, *wp_p = nullptr;
    cudaGetSymbolAddress((void**)&qkv_p, g_qkv);
    cudaGetSymbolAddress((void**)&att_p, g_att);
    cudaGetSymbolAddress((void**)&wq_p, g_wq);
    cudaGetSymbolAddress((void**)&wp_p, g_wp);

    const int smem_bytes = (2 * 4608 + 2 * 3456) * 4;   // 64512
    cudaFuncSetAttribute(gemm_mma<QKVN, true>,  cudaFuncAttributeMaxDynamicSharedMemorySize, smem_bytes);
    cudaFuncSetAttribute(gemm_mma<CDIM, false>, cudaFuncAttributeMaxDynamicSharedMemorySize, smem_bytes);

    // 0) round weights to tf32 (tiny)
    round_weights<<<(QKVN * CDIM + 255) / 256, 256>>>(qkv_w, proj_w);

    // 1) QKV GEMM: [262144,192] x [576,192]^T + b   (A rounded per-fragment)
    dim3 g1(QKVN / 96, TOKENS / 128);
    gemm_mma<QKVN, true><<<g1, 256, smem_bytes>>>(x, wq_p, qkv_b, qkv_p);

    // 2) Windowed attention (writes tf32-rounded g_att)
    win_attn<<<NWINS * NHEADS, 128>>>(bias);

    // 3) Proj GEMM: [262144,192] x [192,192]^T + b  (both operands pre-rounded)
    dim3 g3(CDIM / 96, TOKENS / 128);
    gemm_mma<CDIM, false><<<g3, 256, smem_bytes>>>(att_p, wp_p, proj_b, out);
}

// round 14
// speedup vs baseline: 1.3931x; 1.2641x over previous
#include <cuda_runtime.h>
#include <cuda_fp16.h>
#include <cstdint>

#define TOKENS 262144      // 4 * 256 * 256
#define CDIM   192
#define QKVN   576
#define NHEADS 6
#define NWINS  4096

__device__ __half g_qkv[(size_t)TOKENS * QKVN];   // fp16 qkv
__device__ __half g_att[(size_t)TOKENS * CDIM];   // fp16 attention out
__device__ __half g_wq[(size_t)QKVN * CDIM];      // fp16 qkv_w
__device__ __half g_wp[(size_t)CDIM * CDIM];      // fp16 proj_w

__device__ __forceinline__ uint32_t smem_u32(const void* p) {
    uint32_t a;
    asm("{ .reg .u64 t; cvta.to.shared.u64 t, %1; cvt.u32.u64 %0, t; }" : "=r"(a) : "l"(p));
    return a;
}
__device__ __forceinline__ uint32_t pack_h2(float lo, float hi) {
    __half2 h = __floats2half2_rn(lo, hi);
    return *(uint32_t*)&h;
}
__device__ __forceinline__ void mma_f16(float* c, const uint32_t* a, const uint32_t* b) {
    asm volatile(
        "mma.sync.aligned.m16n8k16.row.col.f32.f16.f16.f32 "
        "{%0,%1,%2,%3}, {%4,%5,%6,%7}, {%8,%9}, {%0,%1,%2,%3};"
        : "+f"(c[0]), "+f"(c[1]), "+f"(c[2]), "+f"(c[3])
        : "r"(a[0]), "r"(a[1]), "r"(a[2]), "r"(a[3]), "r"(b[0]), "r"(b[1]));
}
__device__ __forceinline__ void cpa16(uint32_t dst, const void* src) {
    asm volatile("cp.async.cg.shared.global [%0], [%1], 16;" :: "r"(dst), "l"(src));
}
__device__ __forceinline__ void cpa_commit() {
    asm volatile("cp.async.commit_group;" ::: "memory");
}
template<int N>
__device__ __forceinline__ void cpa_wait() {
    asm volatile("cp.async.wait_group %0;" :: "n"(N) : "memory");
}

// convert weights to fp16 once
__global__ void round_weights(const float* __restrict__ qw, const float* __restrict__ pw)
{
    int i = blockIdx.x * 256 + threadIdx.x;
    if (i < QKVN * CDIM) g_wq[i] = __float2half_rn(qw[i]);
    if (i < CDIM * CDIM) g_wp[i] = __float2half_rn(pw[i]);
}

// epilogue store helpers
__device__ __forceinline__ void store_pair(__half* C, size_t idx, float v0, float v1) {
    ((uint32_t*)C)[idx >> 1] = pack_h2(v0, v1);     // idx even
}
__device__ __forceinline__ void store_pair(float* C, size_t idx, float v0, float v1) {
    *(float2*)(C + idx) = make_float2(v0, v1);
}

// ---------------- fp16 warp-mma GEMM, 2-stage cp.async ----------------
// C[m][n] = sum_k A[m][k]*W[n][k] + bias[n]
// Block 128x96, 8 warps (4m x 2n), warp tile 32x48, BK=32, K=192 (6 slabs).
// W is fp16 (pre-converted). A is fp32 (QKV: converted at fragment load) or fp16 (proj).
// fp16 smem rows: 32 halfs = 16 u32, padded to 20 u32 (80B) -> conflict-free frags.
// fp32 A smem rows: 32 floats padded to 40 (160B) -> conflict-free LDS.64 frags.
template<int NOUT, bool A_HALF, typename AT, typename OT>
__global__ __launch_bounds__(256) void gemm_mma(
    const AT* __restrict__ A, const __half* __restrict__ W,
    const float* __restrict__ bias, OT* __restrict__ C)
{
    extern __shared__ __align__(16) char smc[];
    const int ABUF = A_HALF ? 10240 : 20480;        // per-buffer bytes
    char* Abase = smc;
    char* Bbase = smc + 2 * ABUF;                   // 2 * 7680
    const uint32_t AS = smem_u32(Abase);
    const uint32_t BS = smem_u32(Bbase);

    const int t    = threadIdx.x;
    const int wid  = t >> 5;
    const int lane = t & 31;
    const int bm   = blockIdx.y * 128;
    const int bn   = blockIdx.x * 96;
    const int m0   = (wid >> 1) * 32;
    const int n0   = (wid & 1) * 48;
    const int gr   = lane >> 2;
    const int gc   = lane & 3;

    float acc[2][6][4];
#pragma unroll
    for (int i = 0; i < 2; ++i)
#pragma unroll
        for (int j = 0; j < 6; ++j)
#pragma unroll
            for (int r = 0; r < 4; ++r) acc[i][j][r] = 0.f;

    auto stage = [&](int slab, int buf) {
        const int k0 = slab * 32;
        if (A_HALF) {
#pragma unroll
            for (int p = 0; p < 2; ++p) {           // 512 chunks of 16B
                int ci = t + p * 256;
                int r = ci >> 2, c = ci & 3;
                cpa16(AS + buf * ABUF + r * 80 + c * 16,
                      (const char*)A + ((size_t)(bm + r) * CDIM + k0 + c * 8) * 2);
            }
        } else {
#pragma unroll
            for (int p = 0; p < 4; ++p) {           // 1024 chunks of 16B (fp32)
                int ci = t + p * 256;
                int r = ci >> 3, c = ci & 7;
                cpa16(AS + buf * ABUF + r * 160 + c * 16,
                      (const char*)A + ((size_t)(bm + r) * CDIM + k0 + c * 4) * 4);
            }
        }
#pragma unroll
        for (int p = 0; p < 2; ++p) {               // 384 chunks of 16B
            int ci = t + p * 256;
            if (ci < 384) {
                int r = ci >> 2, c = ci & 3;
                cpa16(BS + buf * 7680 + r * 80 + c * 16,
                      (const char*)W + ((size_t)(bn + r) * CDIM + k0 + c * 8) * 2);
            }
        }
        cpa_commit();
    };

    stage(0, 0);

#pragma unroll
    for (int s = 0; s < 6; ++s) {
        const int buf = s & 1;
        if (s + 1 < 6) stage(s + 1, buf ^ 1);
        if (s + 1 < 6) cpa_wait<1>(); else cpa_wait<0>();
        __syncthreads();

        const float*    Asf = (const float*)(Abase + buf * ABUF);      // stride 40 floats
        const uint32_t* Ash = (const uint32_t*)(Abase + buf * ABUF);   // stride 20 u32
        const uint32_t* Bs  = (const uint32_t*)(Bbase + buf * 7680);   // stride 20 u32

#pragma unroll
        for (int ks = 0; ks < 2; ++ks) {            // 2 x k16 per BK=32
            const int kk2 = ks * 8;                 // u32 offset
            uint32_t af[2][4], bf[6][2];
#pragma unroll
            for (int mi = 0; mi < 2; ++mi) {
                int rb = m0 + mi * 16 + gr;
                if (A_HALF) {
                    af[mi][0] = Ash[rb * 20 + kk2 + gc];
                    af[mi][1] = Ash[(rb + 8) * 20 + kk2 + gc];
                    af[mi][2] = Ash[rb * 20 + kk2 + gc + 4];
                    af[mi][3] = Ash[(rb + 8) * 20 + kk2 + gc + 4];
                } else {
                    float2 p0 = *(const float2*)(Asf + rb * 40 + ks * 16 + 2 * gc);
                    float2 p1 = *(const float2*)(Asf + (rb + 8) * 40 + ks * 16 + 2 * gc);
                    float2 p2 = *(const float2*)(Asf + rb * 40 + ks * 16 + 2 * gc + 8);
                    float2 p3 = *(const float2*)(Asf + (rb + 8) * 40 + ks * 16 + 2 * gc + 8);
                    af[mi][0] = pack_h2(p0.x, p0.y);
                    af[mi][1] = pack_h2(p1.x, p1.y);
                    af[mi][2] = pack_h2(p2.x, p2.y);
                    af[mi][3] = pack_h2(p3.x, p3.y);
                }
            }
#pragma unroll
            for (int ni = 0; ni < 6; ++ni) {
                int nb = n0 + ni * 8 + gr;
                bf[ni][0] = Bs[nb * 20 + kk2 + gc];
                bf[ni][1] = Bs[nb * 20 + kk2 + gc + 4];
            }
#pragma unroll
            for (int mi = 0; mi < 2; ++mi)
#pragma unroll
                for (int ni = 0; ni < 6; ++ni)
                    mma_f16(acc[mi][ni], af[mi], bf[ni]);
        }
        __syncthreads();
    }

#pragma unroll
    for (int mi = 0; mi < 2; ++mi) {
        int mr = bm + m0 + mi * 16 + gr;
#pragma unroll
        for (int ni = 0; ni < 6; ++ni) {
            int nc = bn + n0 + ni * 8 + gc * 2;
            float2 bv = __ldg((const float2*)(bias + nc));
            store_pair(C, (size_t)mr * NOUT + nc,       acc[mi][ni][0] + bv.x, acc[mi][ni][1] + bv.y);
            store_pair(C, (size_t)(mr + 8) * NOUT + nc, acc[mi][ni][2] + bv.x, acc[mi][ni][3] + bv.y);
        }
    }
}

// ---------------- fp16 tensor-core window attention ----------------
// One block (128 thr, 4 warps) per (window, head). Warp w owns rows [16w, 16w+16).
// q,k,v gathered as fp16 (uint4); V stored transposed (vsT[d][tok]) for PV B-frags.
// scale folded into the S epilogue (s*scale + bias).
__global__ __launch_bounds__(128) void win_attn(const float* __restrict__ bias)
{
    __shared__ __align__(16) uint32_t qs_[64 * 20];   // [tok][16 u32 +4 pad]
    __shared__ __align__(16) uint32_t ks_[64 * 20];
    __shared__ __align__(16) uint32_t vsT[32 * 36];   // [d][32 u32 +4 pad]
    __shared__ __align__(16) uint32_t ps_[64 * 36];   // probs fp16 [tok][32 u32 +4 pad]

    const int pair = blockIdx.x;
    const int head = pair % NHEADS;
    const int win  = pair / NHEADS;
    const int b  = win >> 10;
    const int wy = (win >> 5) & 31;
    const int wx = win & 31;

    const int t    = threadIdx.x;
    const int wid  = t >> 5;
    const int lane = t & 31;
    const int gr   = lane >> 2;
    const int gc   = lane & 3;
    const float scale = 0.17677669529663687f;

    // gather: per (token, 16B-chunk): q, k, v streams
#pragma unroll
    for (int i = 0; i < 2; ++i) {
        int idx = t + i * 128;          // 256 = 64 tok * 4 chunks
        int p = idx >> 2;
        int c = idx & 3;
        int h = wy * 8 + (p >> 3);
        int w = wx * 8 + (p & 7);
        int tok = b * 65536 + h * 256 + w;
        const char* gb = (const char*)g_qkv + ((size_t)tok * QKVN + head * 32) * 2;
        uint4 qv = *(const uint4*)(gb + c * 16);
        uint4 kv = *(const uint4*)(gb + 384 + c * 16);   // +CDIM halfs
        uint4 vv = *(const uint4*)(gb + 768 + c * 16);   // +2*CDIM halfs
        *(uint4*)(qs_ + p * 20 + c * 4) = qv;
        *(uint4*)(ks_ + p * 20 + c * 4) = kv;
        const unsigned short* us = (const unsigned short*)&vv;
#pragma unroll
        for (int j = 0; j < 8; ++j) {
            int d = c * 8 + j;
            ((unsigned short*)vsT)[d * 72 + p] = us[j];
        }
    }
    __syncthreads();

    // S = q @ k^T  (warp: 16 rows x 64 cols), K=32 -> 2 k16 steps, 8 n-tiles
    const int m0 = wid * 16;
    float s[8][4];
#pragma unroll
    for (int ni = 0; ni < 8; ++ni)
#pragma unroll
        for (int r = 0; r < 4; ++r) s[ni][r] = 0.f;

#pragma unroll
    for (int ks = 0; ks < 2; ++ks) {
        const int kk2 = ks * 8;
        uint32_t a[4];
        a[0] = qs_[(m0 + gr) * 20 + kk2 + gc];
        a[1] = qs_[(m0 + gr + 8) * 20 + kk2 + gc];
        a[2] = qs_[(m0 + gr) * 20 + kk2 + gc + 4];
        a[3] = qs_[(m0 + gr + 8) * 20 + kk2 + gc + 4];
#pragma unroll
        for (int ni = 0; ni < 8; ++ni) {
            uint32_t bfr[2];
            bfr[0] = ks_[(ni * 8 + gr) * 20 + kk2 + gc];
            bfr[1] = ks_[(ni * 8 + gr) * 20 + kk2 + gc + 4];
            mma_f16(s[ni], a, bfr);
        }
    }

    // logits = s*scale + bias; register softmax (rows r0, r1)
    const int r0 = m0 + gr;
    const int r1 = r0 + 8;
    const float* bp = bias + head * 4096;
    float mx0 = -1e30f, mx1 = -1e30f;
#pragma unroll
    for (int ni = 0; ni < 8; ++ni) {
        float2 b0 = __ldg((const float2*)(bp + r0 * 64 + ni * 8 + gc * 2));
        float2 b1 = __ldg((const float2*)(bp + r1 * 64 + ni * 8 + gc * 2));
        s[ni][0] = s[ni][0] * scale + b0.x; s[ni][1] = s[ni][1] * scale + b0.y;
        s[ni][2] = s[ni][2] * scale + b1.x; s[ni][3] = s[ni][3] * scale + b1.y;
        mx0 = fmaxf(mx0, fmaxf(s[ni][0], s[ni][1]));
        mx1 = fmaxf(mx1, fmaxf(s[ni][2], s[ni][3]));
    }
    mx0 = fmaxf(mx0, __shfl_xor_sync(0xffffffffu, mx0, 1));
    mx0 = fmaxf(mx0, __shfl_xor_sync(0xffffffffu, mx0, 2));
    mx1 = fmaxf(mx1, __shfl_xor_sync(0xffffffffu, mx1, 1));
    mx1 = fmaxf(mx1, __shfl_xor_sync(0xffffffffu, mx1, 2));

    float sum0 = 0.f, sum1 = 0.f;
#pragma unroll
    for (int ni = 0; ni < 8; ++ni) {
        s[ni][0] = __expf(s[ni][0] - mx0);
        s[ni][1] = __expf(s[ni][1] - mx0);
        s[ni][2] = __expf(s[ni][2] - mx1);
        s[ni][3] = __expf(s[ni][3] - mx1);
        sum0 += s[ni][0] + s[ni][1];
        sum1 += s[ni][2] + s[ni][3];
    }
    sum0 += __shfl_xor_sync(0xffffffffu, sum0, 1);
    sum0 += __shfl_xor_sync(0xffffffffu, sum0, 2);
    sum1 += __shfl_xor_sync(0xffffffffu, sum1, 1);
    sum1 += __shfl_xor_sync(0xffffffffu, sum1, 2);
    const float inv0 = 1.f / sum0;
    const float inv1 = 1.f / sum1;

    // P -> fp16 smem (cols ni*8+2gc, +1 -> u32 col ni*4+gc)
#pragma unroll
    for (int ni = 0; ni < 8; ++ni) {
        ps_[r0 * 36 + ni * 4 + gc] = pack_h2(s[ni][0] * inv0, s[ni][1] * inv0);
        ps_[r1 * 36 + ni * 4 + gc] = pack_h2(s[ni][2] * inv1, s[ni][3] * inv1);
    }
    __syncwarp();

    // O = P @ V  (warp: 16 rows x 32 d), K=64 -> 4 k16 steps, 4 n-tiles
    float o[4][4];
#pragma unroll
    for (int ni = 0; ni < 4; ++ni)
#pragma unroll
        for (int r = 0; r < 4; ++r) o[ni][r] = 0.f;

#pragma unroll
    for (int ks = 0; ks < 4; ++ks) {
        const int kk2 = ks * 8;
        uint32_t a[4];
        a[0] = ps_[(m0 + gr) * 36 + kk2 + gc];
        a[1] = ps_[(m0 + gr + 8) * 36 + kk2 + gc];
        a[2] = ps_[(m0 + gr) * 36 + kk2 + gc + 4];
        a[3] = ps_[(m0 + gr + 8) * 36 + kk2 + gc + 4];
#pragma unroll
        for (int ni = 0; ni < 4; ++ni) {
            uint32_t bfr[2];
            bfr[0] = vsT[(ni * 8 + gr) * 36 + kk2 + gc];
            bfr[1] = vsT[(ni * 8 + gr) * 36 + kk2 + gc + 4];
            mma_f16(o[ni], a, bfr);
        }
    }

    // scatter O as fp16 to g_att
    {
        int h0 = wy * 8 + (r0 >> 3), w0 = wx * 8 + (r0 & 7);
        int h1 = wy * 8 + (r1 >> 3), w1 = wx * 8 + (r1 & 7);
        size_t tok0 = (size_t)(b * 65536 + h0 * 256 + w0) * CDIM + head * 32;
        size_t tok1 = (size_t)(b * 65536 + h1 * 256 + w1) * CDIM + head * 32;
        uint32_t* ga = (uint32_t*)g_att;
#pragma unroll
        for (int ni = 0; ni < 4; ++ni) {
            int d = ni * 8 + gc * 2;
            ga[(tok0 + d) >> 1] = pack_h2(o[ni][0], o[ni][1]);
            ga[(tok1 + d) >> 1] = pack_h2(o[ni][2], o[ni][3]);
        }
    }
}

extern "C" void kernel_launch(void* const* d_in, const int* in_sizes, int n_in,
                              void* d_out, int out_size)
{
    const float* x      = (const float*)d_in[0];
    const float* qkv_w  = (const float*)d_in[1];
    const float* qkv_b  = (const float*)d_in[2];
    const float* proj_w = (const float*)d_in[3];
    const float* proj_b = (const float*)d_in[4];
    const float* bias   = (const float*)d_in[5];
    float* out = (float*)d_out;

    __half *qkv_p = nullptr, *att_p = nullptr, *wq_p = nullptr, *wp_p = nullptr;
    cudaGetSymbolAddress((void**)&qkv_p, g_qkv);
    cudaGetSymbolAddress((void**)&att_p, g_att);
    cudaGetSymbolAddress((void**)&wq_p, g_wq);
    cudaGetSymbolAddress((void**)&wp_p, g_wp);

    const int smem_qkv  = 2 * 20480 + 2 * 7680;   // 56320 (A fp32)
    const int smem_proj = 2 * 10240 + 2 * 7680;   // 35840 (A fp16)
    cudaFuncSetAttribute((const void*)gemm_mma<QKVN, false, float, __half>,
                         cudaFuncAttributeMaxDynamicSharedMemorySize, smem_qkv);
    cudaFuncSetAttribute((const void*)gemm_mma<CDIM, true, __half, float>,
                         cudaFuncAttributeMaxDynamicSharedMemorySize, smem_proj);

    // 0) weights -> fp16 (tiny)
    round_weights<<<(QKVN * CDIM + 255) / 256, 256>>>(qkv_w, proj_w);

    // 1) QKV GEMM: fp32 x -> fp16 g_qkv
    dim3 g1(QKVN / 96, TOKENS / 128);
    gemm_mma<QKVN, false, float, __half><<<g1, 256, smem_qkv>>>(x, wq_p, qkv_b, qkv_p);

    // 2) Windowed attention (fp16 in/out)
    win_attn<<<NWINS * NHEADS, 128>>>(bias);

    // 3) Proj GEMM: fp16 g_att -> fp32 out
    dim3 g3(CDIM / 96, TOKENS / 128);
    gemm_mma<CDIM, true, __half, float><<<g3, 256, smem_proj>>>(att_p, wp_p, proj_b, out);
}